// round 6
// baseline (speedup 1.0000x reference)
#include <cuda_runtime.h>

constexpr int PB = 2, PC = 64, PH = 256, PW = 256, IMG = 512;

// Scratch (device globals)
__device__ float g_R[PB * 3 * PH * PW];   // resized img (3 ch)
__device__ float g_S[PB * PH * PW];       // inp . w_comp
__device__ float g_PXo[32 * PW];          // pos basis [o][w]
__device__ float g_PYo[32 * PH];
__device__ float g_T1t[PH * PW];          // T1t[h][w] = sum_o PX[o,w]*PY[o,h]
__device__ float g_GX[3 * PW];            // GX[d][w] = sum_o PX[o,clamp(w+2(d-1))]*PX[o,w]
__device__ float g_GY[3 * PH];
__device__ float g_M[9];                  // w_img^T w_img
__device__ float g_phi[PB * 9 * PH * PW]; // per-neighbor weight, 4.7 MB

// ---------------------------------------------------------------------------
// K1: positional basis
// ---------------------------------------------------------------------------
__global__ __launch_bounds__(256) void pos_kernel(const float* __restrict__ wp) {
    int o = blockIdx.x >> 1;
    int half = blockIdx.x & 1;
    int p = threadIdx.x;
    const float kexp = -0.28782313662425575f;  // -ln(10000)/32
    float acc = 0.f;
    int cbase = half ? 32 : 0;
#pragma unroll
    for (int i = 0; i < 16; i++) {
        float dv = __expf((float)(2 * i) * kexp);
        float s, c;
        __sincosf((float)p * dv, &s, &c);
        acc += wp[o * 64 + cbase + 2 * i] * s + wp[o * 64 + cbase + 2 * i + 1] * c;
    }
    if (half == 0) g_PXo[o * 256 + p] = acc;
    else           g_PYo[o * 256 + p] = acc;
}

// ---------------------------------------------------------------------------
// K2: gram tables
// ---------------------------------------------------------------------------
__global__ void tables_kernel(const float* __restrict__ w_img) {
    int bx = blockIdx.x, t = threadIdx.x;
    if (bx < 256) {
        __shared__ float sPY[32];
        if (t < 32) sPY[t] = g_PYo[t * 256 + bx];
        __syncthreads();
        float a = 0.f;
#pragma unroll
        for (int o = 0; o < 32; o++) a += sPY[o] * g_PXo[o * 256 + t];
        g_T1t[bx * 256 + t] = a;
    } else {
#pragma unroll
        for (int d = 0; d < 3; d++) {
            int q = min(max(t + 2 * (d - 1), 0), 255);
            float ax = 0.f, ay = 0.f;
#pragma unroll
            for (int o = 0; o < 32; o++) {
                ax += g_PXo[o * 256 + q] * g_PXo[o * 256 + t];
                ay += g_PYo[o * 256 + q] * g_PYo[o * 256 + t];
            }
            g_GX[d * 256 + t] = ax;
            g_GY[d * 256 + t] = ay;
        }
        if (t < 9) {
            int i = t / 3, j = t % 3;
            float a = 0.f;
#pragma unroll
            for (int o = 0; o < 32; o++) a += w_img[o * 3 + i] * w_img[o * 3 + j];
            g_M[t] = a;
        }
    }
}

// ---------------------------------------------------------------------------
// K3: prep = S map (blocks 0..511) + bilinear resize (blocks 512..2047)
// ---------------------------------------------------------------------------
__device__ __forceinline__ void make_taps(int o, int* j, float* wt) {
    j[0] = 2 * o - 1; j[1] = 2 * o; j[2] = 2 * o + 1; j[3] = 2 * o + 2;
    wt[0] = 0.125f; wt[1] = 0.375f; wt[2] = 0.375f; wt[3] = 0.125f;
    if (o == 0) {
        j[0] = 0; wt[0] = 0.f;
        wt[1] = 3.f / 7.f; wt[2] = 3.f / 7.f; wt[3] = 1.f / 7.f;
    } else if (o == 255) {
        j[3] = 511; wt[3] = 0.f;
        wt[0] = 1.f / 7.f; wt[1] = 3.f / 7.f; wt[2] = 3.f / 7.f;
    }
}

__global__ __launch_bounds__(256) void prep_kernel(
    const float* __restrict__ inp, const float* __restrict__ img,
    const float* __restrict__ w_comp)
{
    int bx = blockIdx.x;
    if (bx < 512) {
        int idx = bx * 256 + threadIdx.x;
        int b = idx >> 16;
        int pix = idx & 65535;
        const float* ip = inp + ((b * PC) << 16) + pix;
        float acc = 0.f;
#pragma unroll
        for (int c = 0; c < PC; c++)
            acc += __ldg(&w_comp[c]) * __ldg(&ip[c << 16]);
        g_S[(b << 16) + pix] = acc;
    } else {
        int bb = bx - 512;
        int h = bb & 255;
        int bc = bb >> 8;
        int w = threadIdx.x;
        int jh[4], jw[4]; float wh[4], ww[4];
        make_taps(h, jh, wh);
        make_taps(w, jw, ww);
        const float* ip = img + bc * IMG * IMG;
        float acc = 0.f;
#pragma unroll
        for (int a = 0; a < 4; a++) {
            float row = 0.f;
#pragma unroll
            for (int t = 0; t < 4; t++) row += ww[t] * __ldg(&ip[jh[a] * IMG + jw[t]]);
            acc += wh[a] * row;
        }
        g_R[(bc * 256 + h) * 256 + w] = acc;
    }
}

// ---------------------------------------------------------------------------
// K4: phi kernel — k-parallel: one thread per (b, k, pixel).
//   grid (256, 18): y = b*9 + k, x*256+tid = pixel.
//   OOB neighbors produce finite garbage; agg's zero inp-halo kills them.
// ---------------------------------------------------------------------------
__global__ __launch_bounds__(256) void phi_kernel() {
    const int bk = blockIdx.y;
    const int b = bk / 9;
    const int k = bk - b * 9;
    const int pix = blockIdx.x * 256 + threadIdx.x;   // 0..65535
    const int h = pix >> 8;
    const int w = pix & 255;

    const float* Rb = g_R + ((b * 3) << 16);
    const float* Sb = g_S + (b << 16);

    float r0 = __ldg(&Rb[pix]);
    float r1 = __ldg(&Rb[65536 + pix]);
    float r2 = __ldg(&Rb[131072 + pix]);
    float mc0 = __ldg(&g_M[0]) * r0 + __ldg(&g_M[1]) * r1 + __ldg(&g_M[2]) * r2;
    float mc1 = __ldg(&g_M[3]) * r0 + __ldg(&g_M[4]) * r1 + __ldg(&g_M[5]) * r2;
    float mc2 = __ldg(&g_M[6]) * r0 + __ldg(&g_M[7]) * r1 + __ldg(&g_M[8]) * r2;

    const int di = k / 3, dj = k - 3 * di;
    const int hn = min(max(h + 2 * di - 2, 0), 255);
    const int wn = min(max(w + 2 * dj - 2, 0), 255);
    const int nb = (hn << 8) + wn;

    float fs = __ldg(&Rb[nb]) * mc0 + __ldg(&Rb[65536 + nb]) * mc1
             + __ldg(&Rb[131072 + nb]) * mc2;
    fs += __ldg(&g_GX[dj * 256 + w]) + __ldg(&g_GY[di * 256 + h]);
    fs += __ldg(&g_T1t[(h << 8) + wn]) + __ldg(&g_T1t[(hn << 8) + w]);
    float s = __ldg(&Sb[nb]);
    g_phi[(bk << 16) + pix] = fs * (1.f / (1.f + __expf(-s)));
}

// ---------------------------------------------------------------------------
// K5: aggregation.  Tile 28(w) x 16(h), 2 output rows per thread,
//   16 channels per block (4-way split).  grid (10, 16, 8).
//   ONE __syncthreads per block.
// ---------------------------------------------------------------------------
constexpr int TW = 28, TH = 16;
constexpr int SW = 32, SH = 20;
constexpr int CCH = 16;

__global__ __launch_bounds__(256) void agg_kernel(
    const float* __restrict__ inp, float* __restrict__ out)
{
    const int z  = blockIdx.z;
    const int b  = z >> 2;
    const int ch0 = (z & 3) * CCH;
    const int h0 = blockIdx.y * TH;
    const int w0 = blockIdx.x * TW;
    const int tid = threadIdx.x;
    const int tx = tid & 31;
    const int ty = tid >> 5;      // 0..7

    __shared__ float sT[CCH][SH][SW];

    const int gw = w0 - 2 + tx;
    const bool vw = (unsigned)gw < (unsigned)PW;
    // loader rows: ty, ty+8, and (ty<4) ty+16  -> 20 rows
    const int gh0 = h0 - 2 + ty;
    const int gh1 = gh0 + 8;
    const int gh2 = gh0 + 16;
    const bool vh0 = (unsigned)gh0 < (unsigned)PH;
    const bool vh1 = (unsigned)gh1 < (unsigned)PH;
    const bool vh2 = (unsigned)gh2 < (unsigned)PH;

    const bool active = (tx < TW) && (w0 + tx < PW);
    const int hA = h0 + ty, hB = hA + 8;
    const int w = w0 + tx;
    const int ctrA = (hA << 8) + w;
    const int ctrB = (hB << 8) + w;

    // ---- phi loads (both output rows) ----
    float phiA[9], phiB[9];
    if (active) {
        const float* pb = g_phi + ((b * 9) << 16);
#pragma unroll
        for (int k = 0; k < 9; k++) {
            phiA[k] = __ldg(&pb[(k << 16) + ctrA]);
            phiB[k] = __ldg(&pb[(k << 16) + ctrB]);
        }
    }

    // ---- stage inp tile (zero halo) ----
    const int ibase = ((b * PC + ch0) << 16);
#pragma unroll
    for (int c = 0; c < CCH; c++) {
        const int cofs = ibase + (c << 16);
        sT[c][ty][tx]      = (vw && vh0) ? __ldg(&inp[cofs + (gh0 << 8) + gw]) : 0.f;
        sT[c][ty + 8][tx]  = (vw && vh1) ? __ldg(&inp[cofs + (gh1 << 8) + gw]) : 0.f;
        if (ty < 4)
            sT[c][ty + 16][tx] = (vw && vh2) ? __ldg(&inp[cofs + (gh2 << 8) + gw]) : 0.f;
    }
    __syncthreads();

    // ---- compute ----
    if (active) {
        const int obase = ((b * PC + ch0) << 16);
#pragma unroll
        for (int c = 0; c < CCH; c++) {
            float accA = 0.f, accB = 0.f;
#pragma unroll
            for (int k = 0; k < 9; k++) {
                const int rr = 2 * (k / 3);
                const int cc = tx + 2 * (k % 3);
                accA += phiA[k] * sT[c][ty + rr][cc];
                accB += phiB[k] * sT[c][ty + 8 + rr][cc];
            }
            out[obase + (c << 16) + ctrA] = accA;
            out[obase + (c << 16) + ctrB] = accB;
        }
    }
}

// ---------------------------------------------------------------------------
extern "C" void kernel_launch(void* const* d_in, const int* in_sizes, int n_in,
                              void* d_out, int out_size)
{
    const float* inp    = (const float*)d_in[0];   // [2,64,256,256]
    const float* img    = (const float*)d_in[1];   // [2,3,512,512]
    const float* w_pos  = (const float*)d_in[2];   // [32,64]
    const float* w_img  = (const float*)d_in[3];   // [32,3]
    const float* w_comp = (const float*)d_in[4];   // [64]
    float* out = (float*)d_out;

    pos_kernel<<<64, 256>>>(w_pos);
    tables_kernel<<<257, 256>>>(w_img);
    prep_kernel<<<2048, 256>>>(inp, img, w_comp);
    dim3 pgrid(256, PB * 9);
    phi_kernel<<<pgrid, 256>>>();
    dim3 grid((PW + TW - 1) / TW, PH / TH, PB * 4);   // 10 x 16 x 8 = 1280
    agg_kernel<<<grid, 256>>>(inp, out);
}